// round 16
// baseline (speedup 1.0000x reference)
#include <cuda_runtime.h>
#include <cuda_bf16.h>
#include <cstdint>
#include <math.h>

typedef unsigned int       u32;
typedef unsigned long long u64;

#define Bq  32
#define Sq  256
#define Tq  32
#define TQn 31
#define Vq  32000
#define Eq  128
#define Hq  256
#define HDq 512

// ---------------- scratch (device globals; no allocation) ----------------
__device__ float d_X[Sq*Bq*2*Eq];
__device__ float d_xprojF[Sq*Bq*4*Hq];
__device__ float d_xprojB[Sq*Bq*4*Hq];
__device__ float d_ENC[Sq*Bq*2*Hq];
__device__ float d_encproj[Sq*Bq*Hq];
__device__ float d_hT[2][2][Hq*Bq];
__device__ float d_cT[2][Hq*Bq];
__device__ float d_hdT[2][HDq*Bq];
__device__ float d_qxT[TQn*Eq*Bq];
__device__ float d_Wcomb[4*HDq*HDq];
__device__ float d_Z[TQn*Bq*2*HDq];        // [(b*31+t), 1024]
__device__ float d_hp[Bq*Hq];
__device__ float d_scoresG[Bq*Sq];

// bf16 split operands for the big projection A-side (plain row-major)
__device__ __align__(16) __nv_bfloat16 d_Ahi[1024*1024];
__device__ __align__(16) __nv_bfloat16 d_Alo[1024*1024];

// Double-buffered exact-match flag barriers (replay-safe, race-free).
__device__ unsigned e_flags[2][2][128][32];  // [arr][dir][block][pad]
__device__ unsigned d_flags[2][128][32];     // [arr][block][pad]

__device__ __forceinline__ float sigm(float x){ return 1.0f/(1.0f+expf(-x)); }
__device__ __forceinline__ float tanh_(float x){ return 1.0f - 2.0f/(expf(2.0f*x)+1.0f); }
__device__ __forceinline__ float tanha(float x){ float y; asm("tanh.approx.f32 %0, %1;" : "=f"(y) : "f"(x)); return y; }

// decoder barrier: 128 blocks x 256 threads; threads 0..127 poll one flag each
__device__ __forceinline__ void dec_bar(int blk, int tid, unsigned v){
    volatile unsigned* fl = (volatile unsigned*)&d_flags[v & 1][0][0];
    __syncthreads();
    if (tid == 0){ __threadfence(); fl[blk*32] = v; }
    if (tid < 128){ while (fl[tid*32] != v) {} }
    __syncthreads();
}

// ---------------- setup: embeddings, Wcomb ----------------
__global__ void k_setup(const int* __restrict__ ctx, const int* __restrict__ mark,
                        const int* __restrict__ qid,
                        const float* __restrict__ embed, const float* __restrict__ membed,
                        const float* __restrict__ Wd_ih, const float* __restrict__ Wd_hh)
{
    const int NX = Sq*Bq*256;
    const int NQ = TQn*Eq*Bq;
    const int NW = 4*HDq*HDq;
    const int total = NX + NQ + NW;
    for (int idx = blockIdx.x*blockDim.x + threadIdx.x; idx < total; idx += gridDim.x*blockDim.x){
        if (idx < NX){
            int row = idx >> 8; int k = idx & 255;
            int s = row >> 5, b = row & 31;
            float v;
            if (k < Eq) v = embed[(size_t)ctx[b*Sq+s]*Eq + k];
            else        v = membed[(size_t)mark[b*Sq+s]*Eq + (k-Eq)];
            d_X[idx] = v;
        } else if (idx < NX+NQ){
            int i = idx - NX;
            int t = i/(Eq*Bq); int r = i%(Eq*Bq); int k = r >> 5; int b = r & 31;
            d_qxT[i] = embed[(size_t)qid[b*Tq+t]*Eq + k];
        } else {
            int i = idx - NX - NQ; int j = i >> 9; int k = i & 511;
            d_Wcomb[i] = Wd_ih[(size_t)j*640 + 128 + k] + Wd_hh[(size_t)j*512 + k];
        }
    }
}

// ---------------- convert Z -> hi/lo bf16 row-major (pad to 1024 rows) ----------------
__global__ void k_cvtA()
{
    const int total = 1024 * 512;
    for (int idx = blockIdx.x*blockDim.x + threadIdx.x; idx < total; idx += gridDim.x*blockDim.x){
        int m = idx >> 9; int kp = idx & 511; int k = kp << 1;
        float v0 = 0.f, v1 = 0.f;
        if (m < TQn*Bq){
            v0 = d_Z[(size_t)m*1024 + k];
            v1 = d_Z[(size_t)m*1024 + k + 1];
        }
        __nv_bfloat16 h0 = __float2bfloat16(v0), h1 = __float2bfloat16(v1);
        __nv_bfloat16 l0 = __float2bfloat16(v0 - __bfloat162float(h0));
        __nv_bfloat16 l1 = __float2bfloat16(v1 - __bfloat162float(h1));
        *(__nv_bfloat162*)(d_Ahi + (size_t)m*1024 + k) = __halves2bfloat162(h0, h1);
        *(__nv_bfloat162*)(d_Alo + (size_t)m*1024 + k) = __halves2bfloat162(l0, l1);
    }
}

// ---------------- mma.sync bf16 output projection (B converted in-kernel) ----------------
#define ASTR 40
__device__ __forceinline__ void mma_bf16(float* c, u32 a0, u32 a1, u32 a2, u32 a3, u32 b0, u32 b1){
    asm volatile(
        "mma.sync.aligned.m16n8k16.row.col.f32.bf16.bf16.f32 "
        "{%0,%1,%2,%3}, {%4,%5,%6,%7}, {%8,%9}, {%0,%1,%2,%3};"
        : "+f"(c[0]), "+f"(c[1]), "+f"(c[2]), "+f"(c[3])
        : "r"(a0), "r"(a1), "r"(a2), "r"(a3), "r"(b0), "r"(b1));
}
__global__ void __launch_bounds__(256)
k_gemm_mma(const float* __restrict__ O_w, const float* __restrict__ O_b,
           float* __restrict__ out)
{
    __shared__ __nv_bfloat16 sA[2][128*ASTR];
    __shared__ __nv_bfloat16 sB[2][128*ASTR];
    int tid = threadIdx.x;
    int warp = tid >> 5, lane = tid & 31;
    int bm = blockIdx.x, bn = blockIdx.y;
    int wm = warp >> 1, wn = warp & 1;
    int r = lane >> 2, cp = (lane & 3) << 1;

    float acc[2][8][4];
    #pragma unroll
    for (int i=0;i<2;i++)
        #pragma unroll
        for (int j=0;j<8;j++){ acc[i][j][0]=0.f; acc[i][j][1]=0.f; acc[i][j][2]=0.f; acc[i][j][3]=0.f; }

    for (int kc = 0; kc < 1024; kc += 32){
        for (int i = tid; i < 512; i += 256){
            int row = i >> 2, seg = i & 3;
            size_t ga = ((size_t)(bm*128+row))*1024 + kc;
            *(uint4*)&sA[0][row*ASTR + seg*8] = ((const uint4*)(d_Ahi + ga))[seg];
            *(uint4*)&sA[1][row*ASTR + seg*8] = ((const uint4*)(d_Alo + ga))[seg];
        }
        for (int i = tid; i < 1024; i += 256){
            int row = i >> 3, seg = i & 7;
            float4 v = *(const float4*)(O_w + (size_t)(bn*128+row)*1024 + kc + seg*4);
            __nv_bfloat16 h0 = __float2bfloat16(v.x), h1 = __float2bfloat16(v.y);
            __nv_bfloat16 h2 = __float2bfloat16(v.z), h3 = __float2bfloat16(v.w);
            __nv_bfloat16 l0 = __float2bfloat16(v.x - __bfloat162float(h0));
            __nv_bfloat16 l1 = __float2bfloat16(v.y - __bfloat162float(h1));
            __nv_bfloat16 l2 = __float2bfloat16(v.z - __bfloat162float(h2));
            __nv_bfloat16 l3 = __float2bfloat16(v.w - __bfloat162float(h3));
            int o = row*ASTR + seg*4;
            *(__nv_bfloat162*)&sB[0][o    ] = __halves2bfloat162(h0, h1);
            *(__nv_bfloat162*)&sB[0][o + 2] = __halves2bfloat162(h2, h3);
            *(__nv_bfloat162*)&sB[1][o    ] = __halves2bfloat162(l0, l1);
            *(__nv_bfloat162*)&sB[1][o + 2] = __halves2bfloat162(l2, l3);
        }
        __syncthreads();

        #pragma unroll
        for (int ks = 0; ks < 2; ks++){
            int k0 = ks*16;
            u32 af[2][2][4];
            #pragma unroll
            for (int t = 0; t < 2; t++)
                #pragma unroll
                for (int mi = 0; mi < 2; mi++){
                    int ar = wm*32 + mi*16 + r;
                    af[t][mi][0] = *(const u32*)&sA[t][(ar  )*ASTR + k0 + cp    ];
                    af[t][mi][1] = *(const u32*)&sA[t][(ar+8)*ASTR + k0 + cp    ];
                    af[t][mi][2] = *(const u32*)&sA[t][(ar  )*ASTR + k0 + cp + 8];
                    af[t][mi][3] = *(const u32*)&sA[t][(ar+8)*ASTR + k0 + cp + 8];
                }
            u32 bf[2][8][2];
            #pragma unroll
            for (int t = 0; t < 2; t++)
                #pragma unroll
                for (int ni = 0; ni < 8; ni++){
                    int br = wn*64 + ni*8 + r;
                    bf[t][ni][0] = *(const u32*)&sB[t][br*ASTR + k0 + cp    ];
                    bf[t][ni][1] = *(const u32*)&sB[t][br*ASTR + k0 + cp + 8];
                }
            #pragma unroll
            for (int mi = 0; mi < 2; mi++)
                #pragma unroll
                for (int ni = 0; ni < 8; ni++){
                    float* c = acc[mi][ni];
                    mma_bf16(c, af[0][mi][0], af[0][mi][1], af[0][mi][2], af[0][mi][3],
                             bf[0][ni][0], bf[0][ni][1]);
                    mma_bf16(c, af[0][mi][0], af[0][mi][1], af[0][mi][2], af[0][mi][3],
                             bf[1][ni][0], bf[1][ni][1]);
                    mma_bf16(c, af[1][mi][0], af[1][mi][1], af[1][mi][2], af[1][mi][3],
                             bf[0][ni][0], bf[0][ni][1]);
                }
        }
        __syncthreads();
    }

    #pragma unroll
    for (int mi = 0; mi < 2; mi++){
        #pragma unroll
        for (int ni = 0; ni < 8; ni++){
            int n = bn*128 + wn*64 + ni*8 + cp;
            float2 bias = *(const float2*)(O_b + n);
            int m0 = bm*128 + wm*32 + mi*16 + r;
            if (m0 < TQn*Bq){
                float2 v; v.x = acc[mi][ni][0] + bias.x; v.y = acc[mi][ni][1] + bias.y;
                *(float2*)(out + (size_t)m0*Vq + n) = v;
            }
            int m1 = m0 + 8;
            if (m1 < TQn*Bq){
                float2 v; v.x = acc[mi][ni][2] + bias.x; v.y = acc[mi][ni][3] + bias.y;
                *(float2*)(out + (size_t)m1*Vq + n) = v;
            }
        }
    }
}

// ---------------- generic fp32 GEMM: C[M,N] = A[M,K] * B[N,K]^T + bias ----------------
#define GBM 128
#define GBN 64
#define GBK 16
__global__ void __launch_bounds__(256)
k_gemm(const float* __restrict__ A, int lda,
       const float* __restrict__ Bw, int ldb,
       const float* __restrict__ bias,
       float* __restrict__ C, int ldc,
       int M, int N, int K)
{
    __shared__ float As[GBK][GBM+4];
    __shared__ float Bs[GBK][GBN+4];
    int tid = threadIdx.x;
    int tx = tid & 15, ty = tid >> 4;
    int m0 = blockIdx.y * GBM, n0 = blockIdx.x * GBN;

    float acc[8][4];
    #pragma unroll
    for (int i=0;i<8;i++){ acc[i][0]=0.f;acc[i][1]=0.f;acc[i][2]=0.f;acc[i][3]=0.f; }

    int arow = tid >> 1;
    int ak   = (tid & 1) * 8;
    int brow = tid >> 2;
    int bk   = (tid & 3) * 4;

    for (int k0 = 0; k0 < K; k0 += GBK){
        {
            int gm = m0 + arow;
            float4 v0, v1;
            if (gm < M){
                const float* src = A + (size_t)gm*lda + k0 + ak;
                v0 = *(const float4*)src;
                v1 = *(const float4*)(src+4);
            } else {
                v0 = make_float4(0,0,0,0); v1 = v0;
            }
            As[ak+0][arow]=v0.x; As[ak+1][arow]=v0.y; As[ak+2][arow]=v0.z; As[ak+3][arow]=v0.w;
            As[ak+4][arow]=v1.x; As[ak+5][arow]=v1.y; As[ak+6][arow]=v1.z; As[ak+7][arow]=v1.w;
        }
        {
            int gn = n0 + brow;
            float4 v = *(const float4*)(Bw + (size_t)gn*ldb + k0 + bk);
            Bs[bk+0][brow]=v.x; Bs[bk+1][brow]=v.y; Bs[bk+2][brow]=v.z; Bs[bk+3][brow]=v.w;
        }
        __syncthreads();
        #pragma unroll
        for (int kk = 0; kk < GBK; kk++){
            float4 b4 = *(const float4*)&Bs[kk][tx*4];
            float4 a0 = *(const float4*)&As[kk][ty*8];
            float4 a1 = *(const float4*)&As[kk][ty*8+4];
            float av[8] = {a0.x,a0.y,a0.z,a0.w,a1.x,a1.y,a1.z,a1.w};
            float bv[4] = {b4.x,b4.y,b4.z,b4.w};
            #pragma unroll
            for (int i=0;i<8;i++){
                #pragma unroll
                for (int j=0;j<4;j++) acc[i][j] = fmaf(av[i], bv[j], acc[i][j]);
            }
        }
        __syncthreads();
    }

    float4 bb = make_float4(0,0,0,0);
    if (bias) bb = *(const float4*)(bias + n0 + tx*4);
    #pragma unroll
    for (int i=0;i<8;i++){
        int gm = m0 + ty*8 + i;
        if (gm < M){
            float4 o;
            o.x = acc[i][0]+bb.x; o.y = acc[i][1]+bb.y;
            o.z = acc[i][2]+bb.z; o.w = acc[i][3]+bb.w;
            *(float4*)(C + (size_t)gm*ldc + n0 + tx*4) = o;
        }
    }
}

// ---------------- persistent encoder: 256 blocks x 128 threads, 2 units/block --------
// dir = blk>>7, ublk = blk&127 owns units ublk*2 + {0,1} (8 gate-rows rr = g*2+l).
// Thread: w = tid>>5, sub = lane>>3, r = lane&7. kbase = w*64 + sub*16. part = w*4+sub.
// smem: wt[k*9+rr] 2304 | hs 8192 | red[part*264 + b*8 + r] 4224 | res[b*9+rr] 288
//  = 15008 floats = 60032 bytes  (2 blocks/SM -> 120KB, fits)
#define ENC_SMEM 60032
__global__ void __launch_bounds__(128)
k_enc_persist(const float* __restrict__ Wf_hh, const float* __restrict__ Wb_hh)
{
    extern __shared__ float sm[];
    float* wt  = sm;             // 2304
    float* hs  = sm + 2304;      // 8192
    float* red = sm + 10496;     // 4224
    float* res = sm + 14720;     // 288

    int blk = blockIdx.x, dir = blk >> 7, ublk = blk & 127;
    int tid = threadIdx.x;
    int w = tid >> 5, lane = tid & 31;
    int sub = lane >> 3, r = lane & 7;
    int part = w*4 + sub;
    int lf = tid >> 5;            // tid<64: unit-local 0..1
    int bf = tid & 31;
    const float* __restrict__ Whh = dir ? Wb_hh : Wf_hh;
    const float* __restrict__ xp  = dir ? d_xprojB : d_xprojF;

    // weight load: wt[k*9 + rr], rr = g*2+l -> Whh row g*256 + ublk*2 + l, col k
    for (int i = tid; i < 2048; i += 128){
        int k = i >> 3, rr = i & 7, g = rr >> 1, l = rr & 1;
        wt[k*9 + rr] = Whh[((size_t)(g*256 + ublk*2 + l))*256 + k];
    }
    float c = 0.f;
    if (tid < 64) d_hT[dir][0][(ublk*2 + lf)*32 + bf] = 0.f;

    int kbase = w*64 + sub*16;

    for (int t = 0; t < Sq; t++){
        {   // per-dir flag barrier over 128 blocks (exact-match, double-buffered)
            unsigned v = (unsigned)(t + 1);
            volatile unsigned* fl = (volatile unsigned*)&e_flags[v & 1][dir][0][0];
            __syncthreads();
            if (tid == 0){ __threadfence(); fl[ublk*32] = v; }
            while (fl[tid*32] != v) {}
            __syncthreads();
        }
        int s = dir ? (255 - t) : t;
        float pa0=0.f, pa1=0.f, pa2=0.f, pa3=0.f;
        if (tid < 64){
            const float* bp = xp + ((size_t)(s*32 + bf))*1024 + (ublk*2 + lf);
            pa0 = __ldg(bp); pa1 = __ldg(bp+256); pa2 = __ldg(bp+512); pa3 = __ldg(bp+768);
        }
        // stage h [k][b] (8192 floats, 128 threads x 16 x float4)
        const float* hg = d_hT[dir][t & 1];
        for (int i = tid*4; i < 8192; i += 512)
            *(float4*)(hs + i) = __ldcg((const float4*)(hg + i));
        __syncthreads();

        // outer-product accumulate: acc[b] += w[k,rr] * h[k][b]
        float4 acc[8];
        #pragma unroll
        for (int j = 0; j < 8; j++) acc[j] = make_float4(0.f,0.f,0.f,0.f);
        #pragma unroll
        for (int kk = 0; kk < 16; kk++){
            int k = kbase + kk;
            float wv = wt[k*9 + r];
            const float4* hb = (const float4*)(hs + k*32);
            #pragma unroll
            for (int j = 0; j < 8; j++){
                float4 h4 = hb[j];
                acc[j].x += wv*h4.x; acc[j].y += wv*h4.y;
                acc[j].z += wv*h4.z; acc[j].w += wv*h4.w;
            }
        }
        // partials -> red[part][b][r] (stride 264 per part)
        {
            float* rp = red + part*264 + r;
            #pragma unroll
            for (int j = 0; j < 8; j++){
                rp[(j*4+0)*8] = acc[j].x; rp[(j*4+1)*8] = acc[j].y;
                rp[(j*4+2)*8] = acc[j].z; rp[(j*4+3)*8] = acc[j].w;
            }
        }
        __syncthreads();
        // reduce 16 parts -> res[b*9 + rr]; pair = b*8 + rr
        #pragma unroll
        for (int pp = 0; pp < 2; pp++){
            int pair = tid + pp*128;
            float sum = 0.f;
            #pragma unroll
            for (int p = 0; p < 16; p++) sum += red[p*264 + pair];
            res[(pair >> 3)*9 + (pair & 7)] = sum;
        }
        __syncthreads();
        if (tid < 64){
            float g0 = pa0 + res[bf*9 + 0 + lf];
            float g1 = pa1 + res[bf*9 + 2 + lf];
            float g2 = pa2 + res[bf*9 + 4 + lf];
            float g3 = pa3 + res[bf*9 + 6 + lf];
            float cn = sigm(g1)*c + sigm(g0)*tanh_(g2);
            float hn = sigm(g3)*tanh_(cn);
            c = cn;
            int jj = ublk*2 + lf;
            d_hT[dir][(t&1)^1][jj*32 + bf] = hn;
            d_ENC[((size_t)(s*32 + bf))*512 + dir*256 + jj] = hn;
        }
    }
    if (tid < 64) d_cT[dir][(ublk*2 + lf)*32 + bf] = c;
}

// ---------------- persistent decoder: 128 blocks x 256 threads (R12, unchanged) -------
// smem: wd 10240 ([k][r]) | xh 20480 ([k(640)][b]) | red 8192 | res 544
#define DEC_SMEM 157824
__global__ void __launch_bounds__(256)
k_dec_persist(const float* __restrict__ Wd_ih, const float* __restrict__ bd,
              const float* __restrict__ A1_w,  const float* __restrict__ A1_b,
              const float* __restrict__ A2_w,  const float* __restrict__ A2_b,
              const int*   __restrict__ mask)
{
    extern __shared__ float sm[];
    float* wd  = sm;             // 10240
    float* xh  = sm + 10240;     // 20480: qx at [0,4096), h at [4096,20480)
    float* red = sm + 30720;     // 8192 (also B/C/D scratch)
    float* res = sm + 38912;     // 544

    int blk = blockIdx.x;
    int tid = threadIdx.x;
    int w = tid >> 5, lane = tid & 31;
    int sub = lane >> 4, r = lane & 15;
    int part = w*2 + sub;
    int lf = tid >> 5;           // tid<128: unit-local 0..3
    int bf = tid & 31;

    for (int i = tid; i < 10240; i += 256){
        int k = i >> 4, rr = i & 15, g = rr >> 2, l = rr & 3;
        int row = g*512 + blk*4 + l;
        wd[i] = (k < 128) ? Wd_ih[(size_t)row*640 + k]
                          : d_Wcomb[(size_t)row*512 + (k - 128)];
    }

    float c = 0.f;
    float bd0=0.f, bd1=0.f, bd2=0.f, bd3=0.f;
    if (tid < 128){
        int jj = blk*4 + lf;
        float hv;
        if (jj < Hq){ hv = d_hT[0][0][jj*32+bf];       c = d_cT[0][jj*32+bf]; }
        else        { hv = d_hT[1][0][(jj-Hq)*32+bf];  c = d_cT[1][(jj-Hq)*32+bf]; }
        d_hdT[0][jj*32+bf] = hv;
        bd0 = bd[jj]; bd1 = bd[512+jj]; bd2 = bd[1024+jj]; bd3 = bd[1536+jj];
    }

    int kbase = w*80 + sub*40;

    dec_bar(blk, tid, 1u);   // init h visible to all blocks

    for (int t = 0; t < TQn; t++){
        __syncthreads();     // local: phase D of t-1 done (red reuse)
        {
            const float* qg = d_qxT + (size_t)t*Eq*Bq;
            for (int i = tid*4; i < 4096; i += 1024)
                *(float4*)(xh + i) = *(const float4*)(qg + i);
            const float* hg = d_hdT[t & 1];
            for (int i = tid*4; i < 16384; i += 1024)
                *(float4*)(xh + 4096 + i) = __ldcg((const float4*)(hg + i));
        }
        __syncthreads();

        // ---- Phase A: gates, outer-product ----
        {
            float4 acc[8];
            #pragma unroll
            for (int j = 0; j < 8; j++) acc[j] = make_float4(0.f,0.f,0.f,0.f);
            #pragma unroll 8
            for (int kk = 0; kk < 40; kk++){
                int k = kbase + kk;
                float wv = wd[k*16 + r];
                const float4* hb = (const float4*)(xh + k*32);
                #pragma unroll
                for (int j = 0; j < 8; j++){
                    float4 h4 = hb[j];
                    acc[j].x += wv*h4.x; acc[j].y += wv*h4.y;
                    acc[j].z += wv*h4.z; acc[j].w += wv*h4.w;
                }
            }
            float* rp = red + part*512 + r;
            #pragma unroll
            for (int j = 0; j < 8; j++){
                rp[(j*4+0)*16] = acc[j].x; rp[(j*4+1)*16] = acc[j].y;
                rp[(j*4+2)*16] = acc[j].z; rp[(j*4+3)*16] = acc[j].w;
            }
        }
        __syncthreads();
        #pragma unroll
        for (int pp = 0; pp < 2; pp++){
            int pair = tid + pp*256;
            float sum = 0.f;
            #pragma unroll
            for (int p = 0; p < 16; p++) sum += red[p*512 + pair];
            res[(pair >> 4)*17 + (pair & 15)] = sum;
        }
        __syncthreads();
        if (tid < 128){
            float g0 = bd0 + res[bf*17 + 0*4 + lf];
            float g1 = bd1 + res[bf*17 + 1*4 + lf];
            float g2 = bd2 + res[bf*17 + 2*4 + lf];
            float g3 = bd3 + res[bf*17 + 3*4 + lf];
            float cn = sigm(g1)*c + sigm(g0)*tanh_(g2);
            float hn = sigm(g3)*tanh_(cn);
            c = cn;
            int jj = blk*4 + lf;
            d_hdT[(t&1)^1][jj*32+bf] = hn;
            d_Z[((size_t)bf*TQn + t)*1024 + jj] = hn;
        }
        dec_bar(blk, tid, (unsigned)(t*3 + 2));

        // ---- Phase B: hp = A1_b + h_new . A1_w[:, :512] ----
        {
            const float* hg = d_hdT[(t&1)^1];
            for (int i = tid*4; i < 16384; i += 1024)
                *(float4*)(xh + 4096 + i) = __ldcg((const float4*)(hg + i));
        }
        __syncthreads();
        {
            float accB = 0.f;
            int ml = 0, bb2 = 0, kh = 0, m = 0;
            if (tid < 128){
                ml  = tid >> 6;
                int id6 = tid & 63;
                bb2 = id6 & 31;
                kh  = id6 >> 5;
                m   = blk*2 + ml;
                const float* wB = A1_w + (size_t)m*1024 + kh*256;
                const float* hh = xh + 4096 + kh*256*32;
                #pragma unroll 4
                for (int k = 0; k < 256; k += 4){
                    float4 v = *(const float4*)(wB + k);
                    accB += hh[(k+0)*32+bb2]*v.x + hh[(k+1)*32+bb2]*v.y
                          + hh[(k+2)*32+bb2]*v.z + hh[(k+3)*32+bb2]*v.w;
                }
            }
            __syncthreads();
            if (tid < 128 && kh == 1) red[ml*32 + bb2] = accB;
            __syncthreads();
            if (tid < 128 && kh == 0) d_hp[bb2*256 + m] = accB + red[ml*32 + bb2] + A1_b[m];
        }
        dec_bar(blk, tid, (unsigned)(t*3 + 3));

        // ---- Phase C: scores ----
        {
            int b3   = blk & 31;
            int prt  = blk >> 5;
            float* hps  = red;        // 256
            float* scr2 = red + 256;  // 64
            if (tid < 256) hps[tid] = __ldcg(d_hp + b3*256 + tid);
            __syncthreads();

            float accC = 0.f;
            int sl = tid & 63, mh = (tid >> 6) & 1, sC = prt*64 + sl;
            if (tid < 128){
                const float* ep  = d_encproj + ((size_t)sC*32 + b3)*256 + mh*128;
                const float* aw  = A2_w + mh*128;
                const float* hpp = hps + mh*128;
                #pragma unroll 4
                for (int m = 0; m < 128; m += 4){
                    float4 e4 = *(const float4*)(ep + m);
                    float4 w4 = *(const float4*)(aw + m);
                    accC += tanha(hpp[m+0]+e4.x)*w4.x + tanha(hpp[m+1]+e4.y)*w4.y
                          + tanha(hpp[m+2]+e4.z)*w4.z + tanha(hpp[m+3]+e4.w)*w4.w;
                }
            }
            __syncthreads();
            if (tid < 128 && mh == 1) scr2[sl] = accC;
            __syncthreads();
            if (tid < 128 && mh == 0){
                float sc = accC + scr2[sl] + A2_b[0]
                         + (1.0f - (float)mask[b3*Sq + sC]) * (-1e30f);
                d_scoresG[b3*256 + sC] = sc;
            }
        }
        dec_bar(blk, tid, (unsigned)(t*3 + 4));

        // ---- Phase D: softmax + context (blocks 0..31) ----
        if (blk < 32){
            int b4 = blk;
            float* ss = red;        // 256
            float* r2 = red + 256;  // 8
            if (tid < 256) ss[tid] = __ldcg(d_scoresG + b4*256 + tid);
            __syncthreads();
            float e0 = 0.f, e1 = 0.f;
            if (tid < 128){
                float v = fmaxf(ss[tid], ss[tid+128]);
                #pragma unroll
                for (int o=16;o;o>>=1) v = fmaxf(v, __shfl_xor_sync(0xffffffffu, v, o));
                if ((tid & 31) == 0) r2[tid>>5] = v;
            }
            __syncthreads();
            if (tid < 128){
                float mx = fmaxf(fmaxf(r2[0],r2[1]), fmaxf(r2[2],r2[3]));
                e0 = expf(ss[tid] - mx); e1 = expf(ss[tid+128] - mx);
                float su = e0 + e1;
                #pragma unroll
                for (int o=16;o;o>>=1) su += __shfl_xor_sync(0xffffffffu, su, o);
                if ((tid & 31) == 0) r2[4 + (tid>>5)] = su;
            }
            __syncthreads();
            float inv = 1.0f / (r2[4]+r2[5]+r2[6]+r2[7]);
            __syncthreads();
            if (tid < 128){ ss[tid] = e0*inv; ss[tid+128] = e1*inv; }
            __syncthreads();
            if (tid < 128){
                int d4 = tid*4;
                float4 acc4 = make_float4(0,0,0,0);
                const float* eb = d_ENC + (size_t)b4*512 + d4;
                #pragma unroll 4
                for (int sD = 0; sD < 256; sD++){
                    float a = ss[sD];
                    float4 ev = *(const float4*)(eb + (size_t)sD*32*512);
                    acc4.x += a*ev.x; acc4.y += a*ev.y; acc4.z += a*ev.z; acc4.w += a*ev.w;
                }
                *(float4*)(d_Z + ((size_t)b4*TQn + t)*1024 + 512 + d4) = acc4;
            }
        }
    }
}

// ---------------- host launch ----------------
static void* symaddr(const void* sym){
    void* p = nullptr;
    cudaGetSymbolAddress(&p, sym);
    return p;
}

extern "C" void kernel_launch(void* const* d_in, const int* in_sizes, int n_in,
                              void* d_out, int out_size)
{
    const int*   ctx    = (const int*)  d_in[0];
    const int*   mark   = (const int*)  d_in[1];
    const int*   qid    = (const int*)  d_in[2];
    const int*   mask   = (const int*)  d_in[3];
    const float* embed  = (const float*)d_in[4];
    const float* membed = (const float*)d_in[5];
    const float* Wf_ih  = (const float*)d_in[6];
    const float* Wf_hh  = (const float*)d_in[7];
    const float* bf     = (const float*)d_in[8];
    const float* Wb_ih  = (const float*)d_in[9];
    const float* Wb_hh  = (const float*)d_in[10];
    const float* bb     = (const float*)d_in[11];
    const float* Wd_ih  = (const float*)d_in[12];
    const float* Wd_hh  = (const float*)d_in[13];
    const float* bd     = (const float*)d_in[14];
    const float* A1_w   = (const float*)d_in[15];
    const float* A1_b   = (const float*)d_in[16];
    const float* A2_w   = (const float*)d_in[17];
    const float* A2_b   = (const float*)d_in[18];
    const float* O_w    = (const float*)d_in[19];
    const float* O_b    = (const float*)d_in[20];
    float* out = (float*)d_out;

    float* pX    = (float*)symaddr(d_X);
    float* pxF   = (float*)symaddr(d_xprojF);
    float* pxB   = (float*)symaddr(d_xprojB);
    float* pENC  = (float*)symaddr(d_ENC);
    float* pproj = (float*)symaddr(d_encproj);

    cudaFuncSetAttribute(k_enc_persist, cudaFuncAttributeMaxDynamicSharedMemorySize, ENC_SMEM);
    cudaFuncSetAttribute(k_dec_persist, cudaFuncAttributeMaxDynamicSharedMemorySize, DEC_SMEM);

    // 1. embeddings + Wcomb
    k_setup<<<2048, 256>>>(ctx, mark, qid, embed, membed, Wd_ih, Wd_hh);

    // 2. x-projections (bias folded in)
    k_gemm<<<dim3(1024/GBN, (Sq*Bq)/GBM), 256>>>(pX, 256, Wf_ih, 256, bf, pxF, 1024, Sq*Bq, 1024, 256);
    k_gemm<<<dim3(1024/GBN, (Sq*Bq)/GBM), 256>>>(pX, 256, Wb_ih, 256, bb, pxB, 1024, Sq*Bq, 1024, 256);

    // 3. persistent encoder: 256 blocks x 128 threads (2 units/block)
    k_enc_persist<<<256, 128, ENC_SMEM>>>(Wf_hh, Wb_hh);

    // 4. encoder-side attention projection
    k_gemm<<<dim3(256/GBN, (Sq*Bq)/GBM), 256>>>(pENC, 512, A1_w + 512, 1024, nullptr, pproj, 256, Sq*Bq, 256, 512);

    // 5. persistent decoder (R12 structure)
    k_dec_persist<<<128, 256, DEC_SMEM>>>(Wd_ih, bd, A1_w, A1_b, A2_w, A2_b, mask);

    // 6. Z -> bf16 hi/lo, then mma.sync output projection (B split in-kernel)
    k_cvtA<<<512, 256>>>();
    k_gemm_mma<<<dim3(8, 250), 256>>>(O_w, O_b, out);

    (void)in_sizes; (void)n_in; (void)out_size;
}

// round 17
// speedup vs baseline: 1.1352x; 1.1352x over previous
#include <cuda_runtime.h>
#include <cuda_bf16.h>
#include <cstdint>
#include <math.h>

typedef unsigned int       u32;
typedef unsigned long long u64;

#define Bq  32
#define Sq  256
#define Tq  32
#define TQn 31
#define Vq  32000
#define Eq  128
#define Hq  256
#define HDq 512

// ---------------- scratch (device globals; no allocation) ----------------
__device__ float d_X[Sq*Bq*2*Eq];
__device__ float d_xprojF[Sq*Bq*4*Hq];
__device__ float d_xprojB[Sq*Bq*4*Hq];
__device__ float d_ENC[Sq*Bq*2*Hq];
__device__ float d_encproj[Sq*Bq*Hq];
__device__ float d_hT[2][2][Hq*Bq];
__device__ float d_cT[2][Hq*Bq];
__device__ float d_hdT[2][HDq*Bq];
__device__ float d_qxT[TQn*Eq*Bq];
__device__ float d_Wcomb[4*HDq*HDq];
__device__ float d_Z[TQn*Bq*2*HDq];        // [(b*31+t), 1024]
__device__ float d_hp[Bq*Hq];
__device__ float d_scoresG[Bq*Sq];

// bf16 split operands for the big projection A-side (plain row-major)
__device__ __align__(16) __nv_bfloat16 d_Ahi[1024*1024];
__device__ __align__(16) __nv_bfloat16 d_Alo[1024*1024];

// Double-buffered exact-match flag barriers (replay-safe, race-free).
__device__ unsigned e_flags[2][2][64][32];   // [arr][dir][block][pad]
__device__ unsigned d_flags[2][128][32];     // [arr][block][pad]

__device__ __forceinline__ float sigm(float x){ return 1.0f/(1.0f+expf(-x)); }
__device__ __forceinline__ float tanh_(float x){ return 1.0f - 2.0f/(expf(2.0f*x)+1.0f); }
__device__ __forceinline__ float tanha(float x){ float y; asm("tanh.approx.f32 %0, %1;" : "=f"(y) : "f"(x)); return y; }

// decoder barrier: 128 blocks x 256 threads; threads 0..127 poll one flag each.
// __nanosleep backoff cuts L2 poll-flood from ~16K concurrent spinners.
__device__ __forceinline__ void dec_bar(int blk, int tid, unsigned v){
    volatile unsigned* fl = (volatile unsigned*)&d_flags[v & 1][0][0];
    __syncthreads();
    if (tid == 0){ __threadfence(); fl[blk*32] = v; }
    if (tid < 128){
        while (fl[tid*32] != v) { __nanosleep(40); }
    }
    __syncthreads();
}

// ---------------- setup: embeddings, Wcomb ----------------
__global__ void k_setup(const int* __restrict__ ctx, const int* __restrict__ mark,
                        const int* __restrict__ qid,
                        const float* __restrict__ embed, const float* __restrict__ membed,
                        const float* __restrict__ Wd_ih, const float* __restrict__ Wd_hh)
{
    const int NX = Sq*Bq*256;
    const int NQ = TQn*Eq*Bq;
    const int NW = 4*HDq*HDq;
    const int total = NX + NQ + NW;
    for (int idx = blockIdx.x*blockDim.x + threadIdx.x; idx < total; idx += gridDim.x*blockDim.x){
        if (idx < NX){
            int row = idx >> 8; int k = idx & 255;
            int s = row >> 5, b = row & 31;
            float v;
            if (k < Eq) v = embed[(size_t)ctx[b*Sq+s]*Eq + k];
            else        v = membed[(size_t)mark[b*Sq+s]*Eq + (k-Eq)];
            d_X[idx] = v;
        } else if (idx < NX+NQ){
            int i = idx - NX;
            int t = i/(Eq*Bq); int r = i%(Eq*Bq); int k = r >> 5; int b = r & 31;
            d_qxT[i] = embed[(size_t)qid[b*Tq+t]*Eq + k];
        } else {
            int i = idx - NX - NQ; int j = i >> 9; int k = i & 511;
            d_Wcomb[i] = Wd_ih[(size_t)j*640 + 128 + k] + Wd_hh[(size_t)j*512 + k];
        }
    }
}

// ---------------- convert Z -> hi/lo bf16 row-major (pad to 1024 rows) ----------------
__global__ void k_cvtA()
{
    const int total = 1024 * 512;
    for (int idx = blockIdx.x*blockDim.x + threadIdx.x; idx < total; idx += gridDim.x*blockDim.x){
        int m = idx >> 9; int kp = idx & 511; int k = kp << 1;
        float v0 = 0.f, v1 = 0.f;
        if (m < TQn*Bq){
            v0 = d_Z[(size_t)m*1024 + k];
            v1 = d_Z[(size_t)m*1024 + k + 1];
        }
        __nv_bfloat16 h0 = __float2bfloat16(v0), h1 = __float2bfloat16(v1);
        __nv_bfloat16 l0 = __float2bfloat16(v0 - __bfloat162float(h0));
        __nv_bfloat16 l1 = __float2bfloat16(v1 - __bfloat162float(h1));
        *(__nv_bfloat162*)(d_Ahi + (size_t)m*1024 + k) = __halves2bfloat162(h0, h1);
        *(__nv_bfloat162*)(d_Alo + (size_t)m*1024 + k) = __halves2bfloat162(l0, l1);
    }
}

// ---------------- mma.sync bf16 output projection (B converted in-kernel) ----------------
#define ASTR 40
__device__ __forceinline__ void mma_bf16(float* c, u32 a0, u32 a1, u32 a2, u32 a3, u32 b0, u32 b1){
    asm volatile(
        "mma.sync.aligned.m16n8k16.row.col.f32.bf16.bf16.f32 "
        "{%0,%1,%2,%3}, {%4,%5,%6,%7}, {%8,%9}, {%0,%1,%2,%3};"
        : "+f"(c[0]), "+f"(c[1]), "+f"(c[2]), "+f"(c[3])
        : "r"(a0), "r"(a1), "r"(a2), "r"(a3), "r"(b0), "r"(b1));
}
__global__ void __launch_bounds__(256)
k_gemm_mma(const float* __restrict__ O_w, const float* __restrict__ O_b,
           float* __restrict__ out)
{
    __shared__ __nv_bfloat16 sA[2][128*ASTR];
    __shared__ __nv_bfloat16 sB[2][128*ASTR];
    int tid = threadIdx.x;
    int warp = tid >> 5, lane = tid & 31;
    int bm = blockIdx.x, bn = blockIdx.y;
    int wm = warp >> 1, wn = warp & 1;
    int r = lane >> 2, cp = (lane & 3) << 1;

    float acc[2][8][4];
    #pragma unroll
    for (int i=0;i<2;i++)
        #pragma unroll
        for (int j=0;j<8;j++){ acc[i][j][0]=0.f; acc[i][j][1]=0.f; acc[i][j][2]=0.f; acc[i][j][3]=0.f; }

    for (int kc = 0; kc < 1024; kc += 32){
        for (int i = tid; i < 512; i += 256){
            int row = i >> 2, seg = i & 3;
            size_t ga = ((size_t)(bm*128+row))*1024 + kc;
            *(uint4*)&sA[0][row*ASTR + seg*8] = ((const uint4*)(d_Ahi + ga))[seg];
            *(uint4*)&sA[1][row*ASTR + seg*8] = ((const uint4*)(d_Alo + ga))[seg];
        }
        for (int i = tid; i < 1024; i += 256){
            int row = i >> 3, seg = i & 7;
            float4 v = *(const float4*)(O_w + (size_t)(bn*128+row)*1024 + kc + seg*4);
            __nv_bfloat16 h0 = __float2bfloat16(v.x), h1 = __float2bfloat16(v.y);
            __nv_bfloat16 h2 = __float2bfloat16(v.z), h3 = __float2bfloat16(v.w);
            __nv_bfloat16 l0 = __float2bfloat16(v.x - __bfloat162float(h0));
            __nv_bfloat16 l1 = __float2bfloat16(v.y - __bfloat162float(h1));
            __nv_bfloat16 l2 = __float2bfloat16(v.z - __bfloat162float(h2));
            __nv_bfloat16 l3 = __float2bfloat16(v.w - __bfloat162float(h3));
            int o = row*ASTR + seg*4;
            *(__nv_bfloat162*)&sB[0][o    ] = __halves2bfloat162(h0, h1);
            *(__nv_bfloat162*)&sB[0][o + 2] = __halves2bfloat162(h2, h3);
            *(__nv_bfloat162*)&sB[1][o    ] = __halves2bfloat162(l0, l1);
            *(__nv_bfloat162*)&sB[1][o + 2] = __halves2bfloat162(l2, l3);
        }
        __syncthreads();

        #pragma unroll
        for (int ks = 0; ks < 2; ks++){
            int k0 = ks*16;
            u32 af[2][2][4];
            #pragma unroll
            for (int t = 0; t < 2; t++)
                #pragma unroll
                for (int mi = 0; mi < 2; mi++){
                    int ar = wm*32 + mi*16 + r;
                    af[t][mi][0] = *(const u32*)&sA[t][(ar  )*ASTR + k0 + cp    ];
                    af[t][mi][1] = *(const u32*)&sA[t][(ar+8)*ASTR + k0 + cp    ];
                    af[t][mi][2] = *(const u32*)&sA[t][(ar  )*ASTR + k0 + cp + 8];
                    af[t][mi][3] = *(const u32*)&sA[t][(ar+8)*ASTR + k0 + cp + 8];
                }
            u32 bf[2][8][2];
            #pragma unroll
            for (int t = 0; t < 2; t++)
                #pragma unroll
                for (int ni = 0; ni < 8; ni++){
                    int br = wn*64 + ni*8 + r;
                    bf[t][ni][0] = *(const u32*)&sB[t][br*ASTR + k0 + cp    ];
                    bf[t][ni][1] = *(const u32*)&sB[t][br*ASTR + k0 + cp + 8];
                }
            #pragma unroll
            for (int mi = 0; mi < 2; mi++)
                #pragma unroll
                for (int ni = 0; ni < 8; ni++){
                    float* c = acc[mi][ni];
                    mma_bf16(c, af[0][mi][0], af[0][mi][1], af[0][mi][2], af[0][mi][3],
                             bf[0][ni][0], bf[0][ni][1]);
                    mma_bf16(c, af[0][mi][0], af[0][mi][1], af[0][mi][2], af[0][mi][3],
                             bf[1][ni][0], bf[1][ni][1]);
                    mma_bf16(c, af[1][mi][0], af[1][mi][1], af[1][mi][2], af[1][mi][3],
                             bf[0][ni][0], bf[0][ni][1]);
                }
        }
        __syncthreads();
    }

    #pragma unroll
    for (int mi = 0; mi < 2; mi++){
        #pragma unroll
        for (int ni = 0; ni < 8; ni++){
            int n = bn*128 + wn*64 + ni*8 + cp;
            float2 bias = *(const float2*)(O_b + n);
            int m0 = bm*128 + wm*32 + mi*16 + r;
            if (m0 < TQn*Bq){
                float2 v; v.x = acc[mi][ni][0] + bias.x; v.y = acc[mi][ni][1] + bias.y;
                *(float2*)(out + (size_t)m0*Vq + n) = v;
            }
            int m1 = m0 + 8;
            if (m1 < TQn*Bq){
                float2 v; v.x = acc[mi][ni][2] + bias.x; v.y = acc[mi][ni][3] + bias.y;
                *(float2*)(out + (size_t)m1*Vq + n) = v;
            }
        }
    }
}

// ---------------- generic fp32 GEMM: C[M,N] = A[M,K] * B[N,K]^T + bias ----------------
#define GBM 128
#define GBN 64
#define GBK 16
__global__ void __launch_bounds__(256)
k_gemm(const float* __restrict__ A, int lda,
       const float* __restrict__ Bw, int ldb,
       const float* __restrict__ bias,
       float* __restrict__ C, int ldc,
       int M, int N, int K)
{
    __shared__ float As[GBK][GBM+4];
    __shared__ float Bs[GBK][GBN+4];
    int tid = threadIdx.x;
    int tx = tid & 15, ty = tid >> 4;
    int m0 = blockIdx.y * GBM, n0 = blockIdx.x * GBN;

    float acc[8][4];
    #pragma unroll
    for (int i=0;i<8;i++){ acc[i][0]=0.f;acc[i][1]=0.f;acc[i][2]=0.f;acc[i][3]=0.f; }

    int arow = tid >> 1;
    int ak   = (tid & 1) * 8;
    int brow = tid >> 2;
    int bk   = (tid & 3) * 4;

    for (int k0 = 0; k0 < K; k0 += GBK){
        {
            int gm = m0 + arow;
            float4 v0, v1;
            if (gm < M){
                const float* src = A + (size_t)gm*lda + k0 + ak;
                v0 = *(const float4*)src;
                v1 = *(const float4*)(src+4);
            } else {
                v0 = make_float4(0,0,0,0); v1 = v0;
            }
            As[ak+0][arow]=v0.x; As[ak+1][arow]=v0.y; As[ak+2][arow]=v0.z; As[ak+3][arow]=v0.w;
            As[ak+4][arow]=v1.x; As[ak+5][arow]=v1.y; As[ak+6][arow]=v1.z; As[ak+7][arow]=v1.w;
        }
        {
            int gn = n0 + brow;
            float4 v = *(const float4*)(Bw + (size_t)gn*ldb + k0 + bk);
            Bs[bk+0][brow]=v.x; Bs[bk+1][brow]=v.y; Bs[bk+2][brow]=v.z; Bs[bk+3][brow]=v.w;
        }
        __syncthreads();
        #pragma unroll
        for (int kk = 0; kk < GBK; kk++){
            float4 b4 = *(const float4*)&Bs[kk][tx*4];
            float4 a0 = *(const float4*)&As[kk][ty*8];
            float4 a1 = *(const float4*)&As[kk][ty*8+4];
            float av[8] = {a0.x,a0.y,a0.z,a0.w,a1.x,a1.y,a1.z,a1.w};
            float bv[4] = {b4.x,b4.y,b4.z,b4.w};
            #pragma unroll
            for (int i=0;i<8;i++){
                #pragma unroll
                for (int j=0;j<4;j++) acc[i][j] = fmaf(av[i], bv[j], acc[i][j]);
            }
        }
        __syncthreads();
    }

    float4 bb = make_float4(0,0,0,0);
    if (bias) bb = *(const float4*)(bias + n0 + tx*4);
    #pragma unroll
    for (int i=0;i<8;i++){
        int gm = m0 + ty*8 + i;
        if (gm < M){
            float4 o;
            o.x = acc[i][0]+bb.x; o.y = acc[i][1]+bb.y;
            o.z = acc[i][2]+bb.z; o.w = acc[i][3]+bb.w;
            *(float4*)(C + (size_t)gm*ldc + n0 + tx*4) = o;
        }
    }
}

// ---------------- persistent encoder: R12-exact (128 blocks x 256 threads) -----------
// smem: wt 4096 | hs 8192 | red 8192 | res 544
#define ENC_SMEM 84096
__global__ void __launch_bounds__(256)
k_enc_persist(const float* __restrict__ Wf_hh, const float* __restrict__ Wb_hh)
{
    extern __shared__ float sm[];
    float* wt  = sm;
    float* hs  = sm + 4096;
    float* red = sm + 12288;
    float* res = sm + 20480;

    int blk = blockIdx.x, dir = blk >> 6, ublk = blk & 63;
    int tid = threadIdx.x;
    int w = tid >> 5, lane = tid & 31;
    int sub = lane >> 4, r = lane & 15;
    int part = w*2 + sub;
    int lf = tid >> 5;            // tid<128: unit-local 0..3
    int bf = tid & 31;
    const float* __restrict__ Whh = dir ? Wb_hh : Wf_hh;
    const float* __restrict__ xp  = dir ? d_xprojB : d_xprojF;

    for (int i = tid; i < 4096; i += 256){
        int k = i >> 4, rr = i & 15, g = rr >> 2, l = rr & 3;
        wt[i] = Whh[((size_t)(g*256 + ublk*4 + l))*256 + k];
    }
    float c = 0.f;
    if (tid < 128) d_hT[dir][0][(ublk*4 + lf)*32 + bf] = 0.f;

    int kbase = w*32 + sub*16;

    for (int t = 0; t < Sq; t++){
        {   // per-dir flag barrier (exact-match, double-buffered)
            unsigned v = (unsigned)(t + 1);
            volatile unsigned* fl = (volatile unsigned*)&e_flags[v & 1][dir][0][0];
            __syncthreads();
            if (tid == 0){ __threadfence(); fl[ublk*32] = v; }
            if (tid < 64){ while (fl[tid*32] != v) {} }
            __syncthreads();
        }
        int s = dir ? (255 - t) : t;
        float pa0=0.f, pa1=0.f, pa2=0.f, pa3=0.f;
        if (tid < 128){
            const float* bp = xp + ((size_t)(s*32 + bf))*1024 + (ublk*4 + lf);
            pa0 = __ldg(bp); pa1 = __ldg(bp+256); pa2 = __ldg(bp+512); pa3 = __ldg(bp+768);
        }
        // stage h [k][b]
        const float* hg = d_hT[dir][t & 1];
        for (int i = tid*4; i < 8192; i += 1024)
            *(float4*)(hs + i) = __ldcg((const float4*)(hg + i));
        __syncthreads();

        // outer-product accumulate: acc[b] += w[k,r] * h[k][b]
        float4 acc[8];
        #pragma unroll
        for (int j = 0; j < 8; j++) acc[j] = make_float4(0.f,0.f,0.f,0.f);
        #pragma unroll
        for (int kk = 0; kk < 16; kk++){
            int k = kbase + kk;
            float wv = wt[k*16 + r];
            const float4* hb = (const float4*)(hs + k*32);
            #pragma unroll
            for (int j = 0; j < 8; j++){
                float4 h4 = hb[j];
                acc[j].x += wv*h4.x; acc[j].y += wv*h4.y;
                acc[j].z += wv*h4.z; acc[j].w += wv*h4.w;
            }
        }
        // partials -> red[part][b][r]
        {
            float* rp = red + part*512 + r;
            #pragma unroll
            for (int j = 0; j < 8; j++){
                rp[(j*4+0)*16] = acc[j].x; rp[(j*4+1)*16] = acc[j].y;
                rp[(j*4+2)*16] = acc[j].z; rp[(j*4+3)*16] = acc[j].w;
            }
        }
        __syncthreads();
        // reduce 16 parts -> res[b*17+r]
        #pragma unroll
        for (int pp = 0; pp < 2; pp++){
            int pair = tid + pp*256;
            float sum = 0.f;
            #pragma unroll
            for (int p = 0; p < 16; p++) sum += red[p*512 + pair];
            res[(pair >> 4)*17 + (pair & 15)] = sum;
        }
        __syncthreads();
        if (tid < 128){
            float g0 = pa0 + res[bf*17 + 0*4 + lf];
            float g1 = pa1 + res[bf*17 + 1*4 + lf];
            float g2 = pa2 + res[bf*17 + 2*4 + lf];
            float g3 = pa3 + res[bf*17 + 3*4 + lf];
            float cn = sigm(g1)*c + sigm(g0)*tanh_(g2);
            float hn = sigm(g3)*tanh_(cn);
            c = cn;
            int jj = ublk*4 + lf;
            d_hT[dir][(t&1)^1][jj*32 + bf] = hn;
            d_ENC[((size_t)(s*32 + bf))*512 + dir*256 + jj] = hn;
        }
    }
    if (tid < 128) d_cT[dir][(ublk*4 + lf)*32 + bf] = c;
}

// ---------------- persistent decoder: 128 blocks x 256 threads ----------------
// R12 structure; h staged once pre-loop + refreshed by phase B (phase A reuses it).
// smem: wd 10240 ([k][r]) | xh 20480 ([k(640)][b]) | red 8192 | res 544
#define DEC_SMEM 157824
__global__ void __launch_bounds__(256)
k_dec_persist(const float* __restrict__ Wd_ih, const float* __restrict__ bd,
              const float* __restrict__ A1_w,  const float* __restrict__ A1_b,
              const float* __restrict__ A2_w,  const float* __restrict__ A2_b,
              const int*   __restrict__ mask)
{
    extern __shared__ float sm[];
    float* wd  = sm;             // 10240
    float* xh  = sm + 10240;     // 20480: qx at [0,4096), h at [4096,20480)
    float* red = sm + 30720;     // 8192 (also B/C/D scratch)
    float* res = sm + 38912;     // 544

    int blk = blockIdx.x;
    int tid = threadIdx.x;
    int w = tid >> 5, lane = tid & 31;
    int sub = lane >> 4, r = lane & 15;
    int part = w*2 + sub;
    int lf = tid >> 5;           // tid<128: unit-local 0..3
    int bf = tid & 31;

    for (int i = tid; i < 10240; i += 256){
        int k = i >> 4, rr = i & 15, g = rr >> 2, l = rr & 3;
        int row = g*512 + blk*4 + l;
        wd[i] = (k < 128) ? Wd_ih[(size_t)row*640 + k]
                          : d_Wcomb[(size_t)row*512 + (k - 128)];
    }

    float c = 0.f;
    float bd0=0.f, bd1=0.f, bd2=0.f, bd3=0.f;
    float a1bias = 0.f;
    if (tid < 128){
        int jj = blk*4 + lf;
        float hv;
        if (jj < Hq){ hv = d_hT[0][0][jj*32+bf];       c = d_cT[0][jj*32+bf]; }
        else        { hv = d_hT[1][0][(jj-Hq)*32+bf];  c = d_cT[1][(jj-Hq)*32+bf]; }
        d_hdT[0][jj*32+bf] = hv;
        bd0 = bd[jj]; bd1 = bd[512+jj]; bd2 = bd[1024+jj]; bd3 = bd[1536+jj];
        a1bias = A1_b[blk*2 + (tid >> 6)];       // phase-B bias (m = blk*2 + ml)
    }
    // phase-C invariants: mask bias + A2 bias, per-thread registers
    float mbias = 0.f;
    {
        int b3 = blk & 31, prt = blk >> 5;
        int sl = tid & 63, mh = (tid >> 6) & 1;
        if (tid < 128 && mh == 0)
            mbias = (1.0f - (float)mask[b3*Sq + prt*64 + sl]) * (-1e30f);
    }
    float a2b = A2_b[0];

    int kbase = w*80 + sub*40;

    dec_bar(blk, tid, 1u);   // init h visible to all blocks

    // stage h_init once; afterwards phase B's stage keeps xh+4096 current
    {
        const float* hg = d_hdT[0];
        for (int i = tid*4; i < 16384; i += 1024)
            *(float4*)(xh + 4096 + i) = __ldcg((const float4*)(hg + i));
    }

    for (int t = 0; t < TQn; t++){
        __syncthreads();     // local: phase D of t-1 done (red reuse); h stage visible
        {
            const float* qg = d_qxT + (size_t)t*Eq*Bq;
            for (int i = tid*4; i < 4096; i += 1024)
                *(float4*)(xh + i) = *(const float4*)(qg + i);
        }
        __syncthreads();

        // ---- Phase A: gates, outer-product (h already in xh+4096) ----
        {
            float4 acc[8];
            #pragma unroll
            for (int j = 0; j < 8; j++) acc[j] = make_float4(0.f,0.f,0.f,0.f);
            #pragma unroll 8
            for (int kk = 0; kk < 40; kk++){
                int k = kbase + kk;
                float wv = wd[k*16 + r];
                const float4* hb = (const float4*)(xh + k*32);
                #pragma unroll
                for (int j = 0; j < 8; j++){
                    float4 h4 = hb[j];
                    acc[j].x += wv*h4.x; acc[j].y += wv*h4.y;
                    acc[j].z += wv*h4.z; acc[j].w += wv*h4.w;
                }
            }
            float* rp = red + part*512 + r;
            #pragma unroll
            for (int j = 0; j < 8; j++){
                rp[(j*4+0)*16] = acc[j].x; rp[(j*4+1)*16] = acc[j].y;
                rp[(j*4+2)*16] = acc[j].z; rp[(j*4+3)*16] = acc[j].w;
            }
        }
        __syncthreads();
        #pragma unroll
        for (int pp = 0; pp < 2; pp++){
            int pair = tid + pp*256;
            float sum = 0.f;
            #pragma unroll
            for (int p = 0; p < 16; p++) sum += red[p*512 + pair];
            res[(pair >> 4)*17 + (pair & 15)] = sum;
        }
        __syncthreads();
        if (tid < 128){
            float g0 = bd0 + res[bf*17 + 0*4 + lf];
            float g1 = bd1 + res[bf*17 + 1*4 + lf];
            float g2 = bd2 + res[bf*17 + 2*4 + lf];
            float g3 = bd3 + res[bf*17 + 3*4 + lf];
            float cn = sigm(g1)*c + sigm(g0)*tanh_(g2);
            float hn = sigm(g3)*tanh_(cn);
            c = cn;
            int jj = blk*4 + lf;
            d_hdT[(t&1)^1][jj*32+bf] = hn;
            d_Z[((size_t)bf*TQn + t)*1024 + jj] = hn;
        }
        dec_bar(blk, tid, (unsigned)(t*3 + 2));

        // ---- Phase B: hp = A1_b + h_new . A1_w[:, :512]  (stages h_new for t+1 too) ----
        {
            const float* hg = d_hdT[(t&1)^1];
            for (int i = tid*4; i < 16384; i += 1024)
                *(float4*)(xh + 4096 + i) = __ldcg((const float4*)(hg + i));
        }
        __syncthreads();
        {
            float accB = 0.f;
            int ml = 0, bb2 = 0, kh = 0, m = 0;
            if (tid < 128){
                ml  = tid >> 6;
                int id6 = tid & 63;
                bb2 = id6 & 31;
                kh  = id6 >> 5;
                m   = blk*2 + ml;
                const float* wB = A1_w + (size_t)m*1024 + kh*256;
                const float* hh = xh + 4096 + kh*256*32;
                #pragma unroll 4
                for (int k = 0; k < 256; k += 4){
                    float4 v = *(const float4*)(wB + k);
                    accB += hh[(k+0)*32+bb2]*v.x + hh[(k+1)*32+bb2]*v.y
                          + hh[(k+2)*32+bb2]*v.z + hh[(k+3)*32+bb2]*v.w;
                }
            }
            __syncthreads();
            if (tid < 128 && kh == 1) red[ml*32 + bb2] = accB;
            __syncthreads();
            if (tid < 128 && kh == 0) d_hp[bb2*256 + m] = accB + red[ml*32 + bb2] + a1bias;
        }
        dec_bar(blk, tid, (unsigned)(t*3 + 3));

        // ---- Phase C: scores ----
        {
            int b3   = blk & 31;
            int prt  = blk >> 5;
            float* hps  = red;        // 256
            float* scr2 = red + 256;  // 64
            if (tid < 256) hps[tid] = __ldcg(d_hp + b3*256 + tid);
            __syncthreads();

            float accC = 0.f;
            int sl = tid & 63, mh = (tid >> 6) & 1, sC = prt*64 + sl;
            if (tid < 128){
                const float* ep  = d_encproj + ((size_t)sC*32 + b3)*256 + mh*128;
                const float* aw  = A2_w + mh*128;
                const float* hpp = hps + mh*128;
                #pragma unroll 4
                for (int m = 0; m < 128; m += 4){
                    float4 e4 = *(const float4*)(ep + m);
                    float4 w4 = *(const float4*)(aw + m);
                    accC += tanha(hpp[m+0]+e4.x)*w4.x + tanha(hpp[m+1]+e4.y)*w4.y
                          + tanha(hpp[m+2]+e4.z)*w4.z + tanha(hpp[m+3]+e4.w)*w4.w;
                }
            }
            __syncthreads();
            if (tid < 128 && mh == 1) scr2[sl] = accC;
            __syncthreads();
            if (tid < 128 && mh == 0){
                float sc = accC + scr2[sl] + a2b + mbias;
                d_scoresG[b3*256 + sC] = sc;
            }
        }
        dec_bar(blk, tid, (unsigned)(t*3 + 4));

        // ---- Phase D: softmax + context (blocks 0..31) ----
        if (blk < 32){
            int b4 = blk;
            float* ss = red;        // 256
            float* r2 = red + 256;  // 8
            if (tid < 256) ss[tid] = __ldcg(d_scoresG + b4*256 + tid);
            __syncthreads();
            float e0 = 0.f, e1 = 0.f;
            if (tid < 128){
                float v = fmaxf(ss[tid], ss[tid+128]);
                #pragma unroll
                for (int o=16;o;o>>=1) v = fmaxf(v, __shfl_xor_sync(0xffffffffu, v, o));
                if ((tid & 31) == 0) r2[tid>>5] = v;
            }
            __syncthreads();
            if (tid < 128){
                float mx = fmaxf(fmaxf(r2[0],r2[1]), fmaxf(r2[2],r2[3]));
                e0 = expf(ss[tid] - mx); e1 = expf(ss[tid+128] - mx);
                float su = e0 + e1;
                #pragma unroll
                for (int o=16;o;o>>=1) su += __shfl_xor_sync(0xffffffffu, su, o);
                if ((tid & 31) == 0) r2[4 + (tid>>5)] = su;
            }
            __syncthreads();
            float inv = 1.0f / (r2[4]+r2[5]+r2[6]+r2[7]);
            __syncthreads();
            if (tid < 128){ ss[tid] = e0*inv; ss[tid+128] = e1*inv; }
            __syncthreads();
            if (tid < 128){
                int d4 = tid*4;
                float4 acc4 = make_float4(0,0,0,0);
                const float* eb = d_ENC + (size_t)b4*512 + d4;
                #pragma unroll 4
                for (int sD = 0; sD < 256; sD++){
                    float a = ss[sD];
                    float4 ev = *(const float4*)(eb + (size_t)sD*32*512);
                    acc4.x += a*ev.x; acc4.y += a*ev.y; acc4.z += a*ev.z; acc4.w += a*ev.w;
                }
                *(float4*)(d_Z + ((size_t)b4*TQn + t)*1024 + 512 + d4) = acc4;
            }
        }
    }
}

// ---------------- host launch ----------------
static void* symaddr(const void* sym){
    void* p = nullptr;
    cudaGetSymbolAddress(&p, sym);
    return p;
}

extern "C" void kernel_launch(void* const* d_in, const int* in_sizes, int n_in,
                              void* d_out, int out_size)
{
    const int*   ctx    = (const int*)  d_in[0];
    const int*   mark   = (const int*)  d_in[1];
    const int*   qid    = (const int*)  d_in[2];
    const int*   mask   = (const int*)  d_in[3];
    const float* embed  = (const float*)d_in[4];
    const float* membed = (const float*)d_in[5];
    const float* Wf_ih  = (const float*)d_in[6];
    const float* Wf_hh  = (const float*)d_in[7];
    const float* bf     = (const float*)d_in[8];
    const float* Wb_ih  = (const float*)d_in[9];
    const float* Wb_hh  = (const float*)d_in[10];
    const float* bb     = (const float*)d_in[11];
    const float* Wd_ih  = (const float*)d_in[12];
    const float* Wd_hh  = (const float*)d_in[13];
    const float* bd     = (const float*)d_in[14];
    const float* A1_w   = (const float*)d_in[15];
    const float* A1_b   = (const float*)d_in[16];
    const float* A2_w   = (const float*)d_in[17];
    const float* A2_b   = (const float*)d_in[18];
    const float* O_w    = (const float*)d_in[19];
    const float* O_b    = (const float*)d_in[20];
    float* out = (float*)d_out;

    float* pX    = (float*)symaddr(d_X);
    float* pxF   = (float*)symaddr(d_xprojF);
    float* pxB   = (float*)symaddr(d_xprojB);
    float* pENC  = (float*)symaddr(d_ENC);
    float* pproj = (float*)symaddr(d_encproj);

    cudaFuncSetAttribute(k_enc_persist, cudaFuncAttributeMaxDynamicSharedMemorySize, ENC_SMEM);
    cudaFuncSetAttribute(k_dec_persist, cudaFuncAttributeMaxDynamicSharedMemorySize, DEC_SMEM);

    // 1. embeddings + Wcomb
    k_setup<<<2048, 256>>>(ctx, mark, qid, embed, membed, Wd_ih, Wd_hh);

    // 2. x-projections (bias folded in)
    k_gemm<<<dim3(1024/GBN, (Sq*Bq)/GBM), 256>>>(pX, 256, Wf_ih, 256, bf, pxF, 1024, Sq*Bq, 1024, 256);
    k_gemm<<<dim3(1024/GBN, (Sq*Bq)/GBM), 256>>>(pX, 256, Wb_ih, 256, bb, pxB, 1024, Sq*Bq, 1024, 256);

    // 3. persistent encoder (R12-exact)
    k_enc_persist<<<128, 256, ENC_SMEM>>>(Wf_hh, Wb_hh);

    // 4. encoder-side attention projection
    k_gemm<<<dim3(256/GBN, (Sq*Bq)/GBM), 256>>>(pENC, 512, A1_w + 512, 1024, nullptr, pproj, 256, Sq*Bq, 256, 512);

    // 5. persistent decoder (single h-stage per step, nanosleep barrier backoff)
    k_dec_persist<<<128, 256, DEC_SMEM>>>(Wd_ih, bd, A1_w, A1_b, A2_w, A2_b, mask);

    // 6. Z -> bf16 hi/lo, then mma.sync output projection (B split in-kernel)
    k_cvtA<<<512, 256>>>();
    k_gemm_mma<<<dim3(8, 250), 256>>>(O_w, O_b, out);

    (void)in_sizes; (void)n_in; (void)out_size;
}